// round 14
// baseline (speedup 1.0000x reference)
#include <cuda_runtime.h>
#include <cuda_bf16.h>
#include <cstdint>

#define BINS 256
#define THREADS 256
#define GRID 1332            // 148 SMs x 3 blocks/SM x 3 waves; 341K threads ->
                             // <=200 values/thread, so u8 counters can't overflow
#define SMEM_BYTES 65536     // 512 rows x 128 B: per-thread byte counters

// Scratch (device globals -> no allocation). Zero-init at load; last block
// resets every launch so each graph replay starts clean.
__device__ unsigned int g_hist[BINS];
__device__ unsigned int g_ticket;

__global__ void __launch_bounds__(THREADS)
hist_kernel(const float* __restrict__ x, long long n,
            float* __restrict__ out, int out_size) {
    extern __shared__ unsigned char h8[];   // 64 KB: A(b,t)=b*128+base(t)
    __shared__ bool is_last;

    const int tid  = threadIdx.x;
    const int warp = tid >> 5;
    const int lane = tid & 31;
    // bank(A) = (A>>2)&31 = lane  -> conflict-free LDS.U8/STS.U8 always.
    const unsigned base = (unsigned)((warp >> 2) * 32768 + lane * 4 + (warp & 3));

    // Zero the 64 KB counter array (16 uint4 per thread).
    uint4* z = (uint4*)h8;
    #pragma unroll
    for (int i = tid; i < SMEM_BYTES / 16; i += THREADS)
        z[i] = make_uint4(0u, 0u, 0u, 0u);
    __syncthreads();

    const long long n4 = n >> 2;
    const float4* __restrict__ x4 = (const float4*)x;
    const long long stride = (long long)GRID * THREADS;
    long long i = (long long)blockIdx.x * THREADS + tid;

    // Per-element: |x|<=4 one FSETP; fmaf(x,32,128)==round((x+4)*32) bit-exact;
    // counter bump is a plain byte RMW in this thread's private slots.
    auto bin1 = [&](float v) {
        if (fabsf(v) <= 4.0f) {
            float t = fmaf(v, 32.0f, 128.0f);
            int idx = __float2int_rd(t);
            idx = min(idx, BINS - 1);
            unsigned a = base + ((unsigned)idx << 7);
            h8[a] = (unsigned char)(h8[a] + 1u);
        }
    };
    auto bin4v = [&](float4 v) { bin1(v.x); bin1(v.y); bin1(v.z); bin1(v.w); };

    // Rolling depth-2 load pipeline (R7 structure).
    if (i + stride < n4) {
        float4 a = x4[i];
        float4 b = x4[i + stride];
        long long j = i + 2 * stride;
        for (; j + stride < n4; j += 2 * stride) {
            float4 c = x4[j];
            float4 d = x4[j + stride];
            bin4v(a);
            bin4v(b);
            a = c;
            b = d;
        }
        bin4v(a);
        bin4v(b);
        i = j;
    }
    for (; i < n4; i += stride)
        bin4v(x4[i]);

    // Scalar tail (n not multiple of 4) — block 0 only.
    if (blockIdx.x == 0) {
        for (long long j = (n4 << 2) + tid; j < n; j += THREADS)
            bin1(x[j]);
    }
    __syncthreads();

    // Block reduce: thread r sums bin r over all 256 threads.
    // Bin r lives in rows r (warps 0-3, byte w&3) and r+256 (warps 4-7),
    // 32 words per row, 4 counters per word -> dp4a with 0x01010101.
    // Bank-staggered word order keeps the reads conflict-free.
    {
        unsigned sum = 0;
        const unsigned char* row0 = h8 + (unsigned)tid * 128u;
        const unsigned char* row1 = h8 + ((unsigned)tid + 256u) * 128u;
        #pragma unroll
        for (int s = 0; s < 32; s++) {
            int w = (lane + s) & 31;
            sum = __dp4a(*(const unsigned int*)(row0 + w * 4), 0x01010101u, sum);
            sum = __dp4a(*(const unsigned int*)(row1 + w * 4), 0x01010101u, sum);
        }
        if (sum) atomicAdd(&g_hist[tid], sum);
    }

    // Last-block finalize: write (h, h) output, reset globals for next replay.
    __threadfence();
    __syncthreads();
    if (tid == 0)
        is_last = (atomicAdd(&g_ticket, 1u) == (unsigned)GRID - 1u);
    __syncthreads();

    if (is_last) {
        __threadfence();
        unsigned int v = g_hist[tid];
        g_hist[tid] = 0u;
        if (tid == 0) g_ticket = 0u;
        float fv = (float)v;
        for (int basei = 0; basei + tid < out_size; basei += BINS)
            out[basei + tid] = fv;
    }
}

extern "C" void kernel_launch(void* const* d_in, const int* in_sizes, int n_in,
                              void* d_out, int out_size) {
    const float* x = (const float*)d_in[0];
    long long n = (long long)in_sizes[0];
    float* out = (float*)d_out;

    static bool attr_set = false;
    if (!attr_set) {
        cudaFuncSetAttribute(hist_kernel,
                             cudaFuncAttributeMaxDynamicSharedMemorySize,
                             SMEM_BYTES);
        attr_set = true;
    }
    hist_kernel<<<GRID, THREADS, SMEM_BYTES>>>(x, n, out, out_size);
}

// round 16
// speedup vs baseline: 1.0334x; 1.0334x over previous
#include <cuda_runtime.h>
#include <cuda_bf16.h>
#include <cstdint>

#define BINS 256
#define THREADS 256
#define GRID 1332            // 148 SMs x 3 blocks/SM x 3 exact waves; 341K threads
                             // -> <=200 elements/thread, u8 counters can't overflow
#define SMEM_BYTES 65536     // 512 rows x 128 B: per-thread byte counters

// Scratch (device globals -> no allocation). Zero-init at load; last block
// resets every launch so each graph replay starts clean.
__device__ unsigned int g_hist[BINS];
__device__ unsigned int g_ticket;

struct F8 { float v[8]; };

// 256-bit global load (LDG.E.256, sm_100+): one instruction, 32 B in flight.
__device__ __forceinline__ F8 ld8(const float* p) {
    F8 r;
    asm volatile("ld.global.v8.f32 {%0,%1,%2,%3,%4,%5,%6,%7}, [%8];"
                 : "=f"(r.v[0]), "=f"(r.v[1]), "=f"(r.v[2]), "=f"(r.v[3]),
                   "=f"(r.v[4]), "=f"(r.v[5]), "=f"(r.v[6]), "=f"(r.v[7])
                 : "l"(p));
    return r;
}

__global__ void __launch_bounds__(THREADS)
hist_kernel(const float* __restrict__ x, long long n,
            float* __restrict__ out, int out_size) {
    extern __shared__ unsigned char h8[];   // 64 KB: A(bin,thread)=bin*128+base
    __shared__ bool is_last;

    const int tid  = threadIdx.x;
    const int warp = tid >> 5;
    const int lane = tid & 31;
    // bank(addr) = (addr>>2)&31 = lane -> LDS.U8/STS.U8 conflict-free always.
    const unsigned base = (unsigned)((warp >> 2) * 32768 + lane * 4 + (warp & 3));

    // Zero the 64 KB counter array.
    uint4* z = (uint4*)h8;
    #pragma unroll
    for (int i = tid; i < SMEM_BYTES / 16; i += THREADS)
        z[i] = make_uint4(0u, 0u, 0u, 0u);
    __syncthreads();

    // Per element: |x|<=4 one FSETP; fmaf(x,32,128)==round((x+4)*32) bit-exact;
    // byte counter bump = LDS.U8 + IADD + STS.U8 (thread-private, no atomics).
    auto bin1 = [&](float v) {
        if (fabsf(v) <= 4.0f) {
            float t = fmaf(v, 32.0f, 128.0f);
            int idx = __float2int_rd(t);
            idx = min(idx, BINS - 1);
            unsigned a = base + ((unsigned)idx << 7);
            h8[a] = (unsigned char)(h8[a] + 1u);
        }
    };
    auto bin8 = [&](const F8& a) {
        #pragma unroll
        for (int k = 0; k < 8; k++) bin1(a.v[k]);
    };

    const long long n8 = n >> 3;                 // 32B tiles
    const long long s  = (long long)GRID * THREADS;
    long long i = (long long)blockIdx.x * THREADS + tid;

    // 3-buffer bin-then-reload pipeline: each 256-bit load flies across the
    // following two bin8 phases (~80 instr) before its buffer is consumed.
    if (i + 2 * s < n8) {
        F8 a = ld8(x + 8 * i);
        F8 b = ld8(x + 8 * (i + s));
        F8 c = ld8(x + 8 * (i + 2 * s));
        long long j = i + 3 * s;
        for (; j + 2 * s < n8; j += 3 * s) {
            bin8(a); a = ld8(x + 8 * j);
            bin8(b); b = ld8(x + 8 * (j + s));
            bin8(c); c = ld8(x + 8 * (j + 2 * s));
        }
        bin8(a); bin8(b); bin8(c);
        for (; j < n8; j += s)                  // <=2 leftover tiles
            bin8(ld8(x + 8 * j));
    } else {
        for (; i < n8; i += s)
            bin8(ld8(x + 8 * i));
    }

    // Scalar tail (n not multiple of 8) — block 0 only.
    if (blockIdx.x == 0) {
        for (long long j = (n8 << 3) + tid; j < n; j += THREADS)
            bin1(x[j]);
    }
    __syncthreads();

    // Block reduce: thread r sums bin r over all 256 threads. Bin r lives in
    // rows r (warps 0-3) and r+256 (warps 4-7); 32 words/row, 4 u8/word ->
    // dp4a(word, 0x01010101). Bank-staggered order keeps reads conflict-free.
    {
        unsigned sum = 0;
        const unsigned char* row0 = h8 + (unsigned)tid * 128u;
        const unsigned char* row1 = h8 + ((unsigned)tid + 256u) * 128u;
        #pragma unroll
        for (int st = 0; st < 32; st++) {
            int w = (lane + st) & 31;
            sum = __dp4a(*(const unsigned int*)(row0 + w * 4), 0x01010101u, sum);
            sum = __dp4a(*(const unsigned int*)(row1 + w * 4), 0x01010101u, sum);
        }
        if (sum) atomicAdd(&g_hist[tid], sum);
    }

    // Last-block finalize: write (h, h) output, reset globals for next replay.
    __threadfence();
    __syncthreads();
    if (tid == 0)
        is_last = (atomicAdd(&g_ticket, 1u) == (unsigned)GRID - 1u);
    __syncthreads();

    if (is_last) {
        __threadfence();
        unsigned int v = g_hist[tid];
        g_hist[tid] = 0u;
        if (tid == 0) g_ticket = 0u;
        float fv = (float)v;
        for (int basei = 0; basei + tid < out_size; basei += BINS)
            out[basei + tid] = fv;
    }
}

extern "C" void kernel_launch(void* const* d_in, const int* in_sizes, int n_in,
                              void* d_out, int out_size) {
    const float* x = (const float*)d_in[0];
    long long n = (long long)in_sizes[0];
    float* out = (float*)d_out;

    static bool attr_set = false;
    if (!attr_set) {
        cudaFuncSetAttribute(hist_kernel,
                             cudaFuncAttributeMaxDynamicSharedMemorySize,
                             SMEM_BYTES);
        attr_set = true;
    }
    hist_kernel<<<GRID, THREADS, SMEM_BYTES>>>(x, n, out, out_size);
}